// round 16
// baseline (speedup 1.0000x reference)
#include <cuda_runtime.h>
#include <cuda_fp16.h>
#include <cstdint>

#define VOCAB 32000
#define EMB   512
#define HID   1024
#define CTXD  2048
#define BATCH 64
#define TSTEPS 64
#define LCTX  64
#define XDIM  (EMB + CTXD)   // 2560
#define G3H   (3 * HID)      // 3072

#define SCALE     256.0f
#define INV_SCALE (1.0f / 65536.0f)

// ---------------------------------------------------------------------------
// Device-global scratch
// ---------------------------------------------------------------------------
__device__ float g_ctxW[BATCH * LCTX * HID];
__device__ float g_ctxP[BATCH * LCTX * G3H];
__device__ float g_gxe [BATCH * TSTEPS * G3H];
__device__ float g_attn[BATCH * LCTX];         // softmaxed attention weights
__device__ float g_gh4 [4][BATCH * G3H];       // K-split quarters of h @ Whh^T
__device__ float g_h   [BATCH * HID];

// fp16 2-way split buffers (hi / lo), pre-scaled by 256
__device__ __half g_ctxs[2][BATCH * LCTX * CTXD];
__device__ __half g_Was [2][HID * CTXD];
__device__ __half g_Wihs[2][G3H * XDIM];
__device__ __half g_embs[2][BATCH * TSTEPS * EMB];

// ---------------------------------------------------------------------------
// helpers
// ---------------------------------------------------------------------------
__device__ __forceinline__ uint32_t smem_u32(const void* p) {
    uint32_t a;
    asm("{ .reg .u64 t; cvta.to.shared.u64 t, %1; cvt.u32.u64 %0, t; }" : "=r"(a) : "l"(p));
    return a;
}

__device__ __forceinline__ void ldmx4(uint32_t& r0, uint32_t& r1, uint32_t& r2, uint32_t& r3,
                                      uint32_t addr) {
    asm volatile("ldmatrix.sync.aligned.m8n8.x4.shared.b16 {%0,%1,%2,%3}, [%4];"
                 : "=r"(r0), "=r"(r1), "=r"(r2), "=r"(r3) : "r"(addr));
}

__device__ __forceinline__ void mma16816h(float* c, const uint32_t* a, const uint32_t* b) {
    asm volatile("mma.sync.aligned.m16n8k16.row.col.f32.f16.f16.f32 "
        "{%0,%1,%2,%3}, {%4,%5,%6,%7}, {%8,%9}, {%0,%1,%2,%3};"
        : "+f"(c[0]), "+f"(c[1]), "+f"(c[2]), "+f"(c[3])
        : "r"(a[0]), "r"(a[1]), "r"(a[2]), "r"(a[3]), "r"(b[0]), "r"(b[1]));
}

__device__ __forceinline__ void cp16(uint32_t dst, const void* src) {
    asm volatile("cp.async.cg.shared.global [%0], [%1], 16;" :: "r"(dst), "l"(src));
}
#define CP_COMMIT() asm volatile("cp.async.commit_group;" ::: "memory")
#define CP_WAIT1()  asm volatile("cp.async.wait_group 1;" ::: "memory")
#define CP_WAIT0()  asm volatile("cp.async.wait_group 0;" ::: "memory")

// ---------------------------------------------------------------------------
// Split fp32 -> 2x fp16 (hi, lo) with x256 pre-scale
// ---------------------------------------------------------------------------
__device__ __forceinline__ void split2(float x, __half& h, __half& l) {
    float xs = x * SCALE;
    h = __float2half_rn(xs);
    float r = xs - __half2float(h);
    l = __float2half_rn(r);
}

__global__ void k_split(const float* __restrict__ s,
                        __half* __restrict__ d0,
                        __half* __restrict__ d1)
{
    int i = blockIdx.x * 256 + threadIdx.x;
    float4 v = ((const float4*)s)[i];
    __half h[4], l[4];
    float x[4] = {v.x, v.y, v.z, v.w};
#pragma unroll
    for (int q = 0; q < 4; q++) split2(x[q], h[q], l[q]);
    ((uint2*)d0)[i] = *(uint2*)h;
    ((uint2*)d1)[i] = *(uint2*)l;
}

__global__ void k_split_emb(const float* __restrict__ emb, const int* __restrict__ tgt)
{
    int row = blockIdx.x;
    int tok = tgt[row];
    int c = threadIdx.x;
    float4 v = ((const float4*)(emb + (size_t)tok * EMB))[c];
    __half h[4], l[4];
    float x[4] = {v.x, v.y, v.z, v.w};
#pragma unroll
    for (int q = 0; q < 4; q++) split2(x[q], h[q], l[q]);
    ((uint2*)(g_embs[0] + (size_t)row * EMB))[c] = *(uint2*)h;
    ((uint2*)(g_embs[1] + (size_t)row * EMB))[c] = *(uint2*)l;
}

// ---------------------------------------------------------------------------
// mma.sync fp16 2-way-split GEMM (3 terms) + fp32 re-accumulation,
// cp.async 2-stage. (Identical to R15, passing at rel_err 1.26e-4.)
// ---------------------------------------------------------------------------
#define ROWB 80
#define TILEB (128 * ROWB)
#define STAGEB (4 * TILEB)
#define GSMEM (2 * STAGEB)

__global__ void __launch_bounds__(256) k_mma_gemm(
    const __half* __restrict__ A1, const __half* __restrict__ A2, int lda,
    const __half* __restrict__ B1, const __half* __restrict__ B2, int ldb,
    int K, const float* __restrict__ bias,
    float* __restrict__ C, int ldc)
{
    extern __shared__ __align__(16) char smem[];

    const int tid = threadIdx.x;
    const int w = tid >> 5, lane = tid & 31;
    const int wm = w >> 2, wn = w & 3;
    const int m0 = blockIdx.y * 128, n0 = blockIdx.x * 128;
    const uint32_t sbase = smem_u32(smem);

    const uint32_t aoff = (uint32_t)(wm * 64 + (lane & 15)) * ROWB + (lane >> 4) * 16;
    const uint32_t boff = (uint32_t)(wn * 32 + ((lane >> 4) & 1) * 8 + (lane & 7)) * ROWB
                        + ((lane >> 3) & 1) * 16;

    const int r0 = tid >> 2, kc0 = tid & 3;
    const int r1 = (tid + 256) >> 2;
    const uint32_t d0 = (uint32_t)r0 * ROWB + kc0 * 16;
    const uint32_t d1 = (uint32_t)r1 * ROWB + kc0 * 16;

    const __half* pa[8] = {
        A1 + (size_t)(m0 + r0) * lda + kc0 * 8, A1 + (size_t)(m0 + r1) * lda + kc0 * 8,
        A2 + (size_t)(m0 + r0) * lda + kc0 * 8, A2 + (size_t)(m0 + r1) * lda + kc0 * 8,
        B1 + (size_t)(n0 + r0) * ldb + kc0 * 8, B1 + (size_t)(n0 + r1) * ldb + kc0 * 8,
        B2 + (size_t)(n0 + r0) * ldb + kc0 * 8, B2 + (size_t)(n0 + r1) * ldb + kc0 * 8 };

    auto issue = [&](int stage, int k0) {
        const uint32_t sb = sbase + stage * STAGEB;
#pragma unroll
        for (int q = 0; q < 4; q++) {
            cp16(sb + q * TILEB + d0, pa[2 * q]     + k0);
            cp16(sb + q * TILEB + d1, pa[2 * q + 1] + k0);
        }
    };

    float master[4][4][4];
#pragma unroll
    for (int i = 0; i < 4; i++)
#pragma unroll
        for (int j = 0; j < 4; j++)
#pragma unroll
            for (int q = 0; q < 4; q++) master[i][j][q] = 0.f;

    const int NC = K / 32;

    issue(0, 0);
    CP_COMMIT();

    for (int c = 0; c < NC; c++) {
        if (c + 1 < NC) {
            issue((c + 1) & 1, (c + 1) * 32);
            CP_COMMIT();
            CP_WAIT1();
        } else {
            CP_WAIT0();
        }
        __syncthreads();

        const uint32_t sb = sbase + (c & 1) * STAGEB;
        const uint32_t sA1 = sb, sA2 = sb + TILEB;
        const uint32_t sB1 = sb + 2 * TILEB, sB2 = sb + 3 * TILEB;

#pragma unroll
        for (int k16 = 0; k16 < 2; k16++) {
            const uint32_t kadd = k16 * 32;
            uint32_t b1[8], b2[8];
            ldmx4(b1[0], b1[1], b1[2], b1[3], sB1 + boff + kadd);
            ldmx4(b1[4], b1[5], b1[6], b1[7], sB1 + boff + kadd + 16 * ROWB);
            ldmx4(b2[0], b2[1], b2[2], b2[3], sB2 + boff + kadd);
            ldmx4(b2[4], b2[5], b2[6], b2[7], sB2 + boff + kadd + 16 * ROWB);
#pragma unroll
            for (int mi = 0; mi < 4; mi++) {
                uint32_t a1[4], a2[4];
                ldmx4(a1[0], a1[1], a1[2], a1[3], sA1 + aoff + mi * 16 * ROWB + kadd);
                ldmx4(a2[0], a2[1], a2[2], a2[3], sA2 + aoff + mi * 16 * ROWB + kadd);
#pragma unroll
                for (int ni = 0; ni < 4; ni++) {
                    float t0[4] = {0.f, 0.f, 0.f, 0.f};
                    float t1[4] = {0.f, 0.f, 0.f, 0.f};
                    mma16816h(t0, a2, b1 + ni * 2);   // ~2^-12
                    mma16816h(t1, a1, b2 + ni * 2);   // ~2^-12 (indep chain)
                    mma16816h(t0, a1, b1 + ni * 2);   // ~1 (only full-mag add)
#pragma unroll
                    for (int q = 0; q < 4; q++)
                        master[mi][ni][q] += t0[q] + t1[q];
                }
            }
        }
        __syncthreads();
    }

    const int lr = lane >> 2, lc = (lane & 3) * 2;
#pragma unroll
    for (int mi = 0; mi < 4; mi++) {
#pragma unroll
        for (int ni = 0; ni < 4; ni++) {
            int n = n0 + wn * 32 + ni * 8 + lc;
            float bv0 = bias ? bias[n]     : 0.f;
            float bv1 = bias ? bias[n + 1] : 0.f;
            int mA = m0 + wm * 64 + mi * 16 + lr;
            float2 v0 = {master[mi][ni][0] * INV_SCALE + bv0,
                         master[mi][ni][1] * INV_SCALE + bv1};
            float2 v1 = {master[mi][ni][2] * INV_SCALE + bv0,
                         master[mi][ni][3] * INV_SCALE + bv1};
            *(float2*)(C + (size_t)mA * ldc + n)       = v0;
            *(float2*)(C + (size_t)(mA + 8) * ldc + n) = v1;
        }
    }
}

// ---------------------------------------------------------------------------
// K_A: per step, 256 CTAs x 512 threads.
//  bx < 192: gh quarter-GEMM (kh = bx & 3, 64-col n-tile, K = 256) — as R15.
//  bx >= 192: scores + softmax ONLY for batch b; writes g_attn[b].
// ---------------------------------------------------------------------------
#define PAD 68

__global__ void __launch_bounds__(512) k_stepA(
    const float* __restrict__ Whh,
    const float* __restrict__ bhh,
    const int* __restrict__ ctx_len)
{
    const int bx = blockIdx.x;
    const int tid = threadIdx.x;

    if (bx < 192) {
        __shared__ __align__(16) float Xs[32 * PAD];
        __shared__ __align__(16) float Ws[32 * PAD];
        const int kh = bx & 3;
        const int n0 = (bx >> 2) * 64;
        const float* A  = g_h + kh * 256;
        const float* Bw = Whh + kh * 256;

        const int tm = tid >> 4, tn = tid & 15;
        const int lrow = tid >> 3, lkc = tid & 7;

        float acc[2][4];
#pragma unroll
        for (int i = 0; i < 2; i++)
#pragma unroll
            for (int j = 0; j < 4; j++) acc[i][j] = 0.f;

        for (int k0 = 0; k0 < 256; k0 += 32) {
            float4 v = *(const float4*)(A + (size_t)lrow * HID + k0 + lkc * 4);
            Xs[(lkc * 4 + 0) * PAD + lrow] = v.x;
            Xs[(lkc * 4 + 1) * PAD + lrow] = v.y;
            Xs[(lkc * 4 + 2) * PAD + lrow] = v.z;
            Xs[(lkc * 4 + 3) * PAD + lrow] = v.w;
            float4 w = *(const float4*)(Bw + (size_t)(n0 + lrow) * HID + k0 + lkc * 4);
            Ws[(lkc * 4 + 0) * PAD + lrow] = w.x;
            Ws[(lkc * 4 + 1) * PAD + lrow] = w.y;
            Ws[(lkc * 4 + 2) * PAD + lrow] = w.z;
            Ws[(lkc * 4 + 3) * PAD + lrow] = w.w;
            __syncthreads();
#pragma unroll
            for (int kk = 0; kk < 32; kk++) {
                float a0 = Xs[kk * PAD + tm * 2];
                float a1 = Xs[kk * PAD + tm * 2 + 1];
                float b[4];
                *(float4*)b = *(const float4*)&Ws[kk * PAD + tn * 4];
#pragma unroll
                for (int j = 0; j < 4; j++) {
                    acc[0][j] = fmaf(a0, b[j], acc[0][j]);
                    acc[1][j] = fmaf(a1, b[j], acc[1][j]);
                }
            }
            __syncthreads();
        }

        float* dst = g_gh4[kh];
#pragma unroll
        for (int i = 0; i < 2; i++) {
            int m = tm * 2 + i;
            int n = n0 + tn * 4;
            float4 v;
            v.x = acc[i][0]; v.y = acc[i][1]; v.z = acc[i][2]; v.w = acc[i][3];
            if (kh == 0) {
                v.x += bhh[n]; v.y += bhh[n + 1]; v.z += bhh[n + 2]; v.w += bhh[n + 3];
            }
            *(float4*)(dst + (size_t)m * G3H + n) = v;
        }
        return;
    }

    // ---- scores + softmax CTA ----
    const int b = bx - 192;
    __shared__ __align__(16) float h_s[HID];
    __shared__ float attn_s[LCTX];

    ((float2*)h_s)[tid] = ((const float2*)(g_h + (size_t)b * HID))[tid];
    __syncthreads();

    const int w = tid >> 5, lane = tid & 31;
    const float4* h4 = (const float4*)h_s;
#pragma unroll
    for (int li = 0; li < 4; li++) {
        const int l = li * 16 + w;
        const float4* cw = (const float4*)(g_ctxW + ((size_t)b * LCTX + l) * HID);
        float s = 0.f;
#pragma unroll 8
        for (int i = lane; i < HID / 4; i += 32) {
            float4 a = h4[i], v = cw[i];
            s += a.x * v.x + a.y * v.y + a.z * v.z + a.w * v.w;
        }
#pragma unroll
        for (int off = 16; off > 0; off >>= 1)
            s += __shfl_xor_sync(0xffffffffu, s, off);
        if (lane == 0) attn_s[l] = s;
    }
    __syncthreads();

    if (tid < 32) {
        int len = ctx_len[b];
        float s0 = (tid < len)      ? attn_s[tid]      : -1e9f;
        float s1 = (tid + 32 < len) ? attn_s[tid + 32] : -1e9f;
        float m = fmaxf(s0, s1);
#pragma unroll
        for (int off = 16; off > 0; off >>= 1)
            m = fmaxf(m, __shfl_xor_sync(0xffffffffu, m, off));
        float e0 = __expf(s0 - m), e1 = __expf(s1 - m);
        float ss = e0 + e1;
#pragma unroll
        for (int off = 16; off > 0; off >>= 1)
            ss += __shfl_xor_sync(0xffffffffu, ss, off);
        g_attn[b * LCTX + tid]      = e0 / ss;
        g_attn[b * LCTX + tid + 32] = e1 / ss;
    }
}

// ---------------------------------------------------------------------------
// K_B: per step, 256 CTAs = (b, quarter) x 256 threads.
// Computes the gxc columns this CTA's GRU elements need (in registers),
// then the fused GRU update + h/out writes. No gxc global roundtrip.
// Thread tid of CTA (b,q) owns h element j = q*256+tid, needing gxc columns
// j, HID+j, 2*HID+j.
// ---------------------------------------------------------------------------
__global__ void __launch_bounds__(256) k_stepB(
    int t, float* __restrict__ out)
{
    __shared__ float attn_s[LCTX];
    const int bx = blockIdx.x;
    const int b = bx >> 2, q = bx & 3;
    const int tid = threadIdx.x;
    const int j = q * 256 + tid;

    if (tid < 64) attn_s[tid] = g_attn[b * LCTX + tid];
    __syncthreads();

    // gxc accumulation straight from ctxP
    float acc0 = 0.f, acc1 = 0.f, acc2 = 0.f;
    const float* base = g_ctxP + ((size_t)b * LCTX) * G3H + j;
#pragma unroll 4
    for (int l = 0; l < LCTX; l++) {
        float a = attn_s[l];
        const float* row = base + (size_t)l * G3H;
        acc0 = fmaf(a, row[0],        acc0);
        acc1 = fmaf(a, row[HID],      acc1);
        acc2 = fmaf(a, row[2 * HID],  acc2);
    }

    // fused GRU
    const float* gxe = g_gxe + (size_t)(b * TSTEPS + t) * G3H;
    float* hp = g_h + (size_t)b * HID;

    float gxr = gxe[j]           + acc0;
    float gxz = gxe[HID + j]     + acc1;
    float gxn = gxe[2 * HID + j] + acc2;
    float ghr = 0.f, ghz = 0.f, ghn = 0.f;
#pragma unroll
    for (int kh = 0; kh < 4; kh++) {
        const float* gh = g_gh4[kh] + (size_t)b * G3H;
        ghr += gh[j];
        ghz += gh[HID + j];
        ghn += gh[2 * HID + j];
    }
    float r = 1.f / (1.f + __expf(-(gxr + ghr)));
    float z = 1.f / (1.f + __expf(-(gxz + ghz)));
    float n = tanhf(gxn + r * ghn);
    float hv = (1.f - z) * n + z * hp[j];

    hp[j] = hv;
    out[((size_t)b * TSTEPS + t) * HID + j] = hv;
    if (t == TSTEPS - 1)
        out[(size_t)BATCH * TSTEPS * HID + (size_t)b * HID + j] = hv;
}

// seed h = h0
__global__ void k_seed(const float* __restrict__ h0)
{
    int i = blockIdx.x * 256 + threadIdx.x;
    g_h[i] = h0[i];
}

// ---------------------------------------------------------------------------
extern "C" void kernel_launch(void* const* d_in, const int* in_sizes, int n_in,
                              void* d_out, int out_size)
{
    const int*   tgt     = (const int*)  d_in[0];
    const float* ctx     = (const float*)d_in[1];
    const float* h0      = (const float*)d_in[2];
    const int*   ctx_len = (const int*)  d_in[3];
    const float* emb     = (const float*)d_in[4];
    const float* Wa      = (const float*)d_in[5];
    const float* Wih     = (const float*)d_in[6];
    const float* Whh     = (const float*)d_in[7];
    const float* bih     = (const float*)d_in[8];
    const float* bhh     = (const float*)d_in[9];
    float* out = (float*)d_out;

    cudaFuncSetAttribute(k_mma_gemm, cudaFuncAttributeMaxDynamicSharedMemorySize, GSMEM);

    float* ctxW = nullptr; cudaGetSymbolAddress((void**)&ctxW, g_ctxW);
    float* ctxP = nullptr; cudaGetSymbolAddress((void**)&ctxP, g_ctxP);
    float* gxe  = nullptr; cudaGetSymbolAddress((void**)&gxe,  g_gxe);

    __half *ctxs, *Was, *Wihs, *embs;
    cudaGetSymbolAddress((void**)&ctxs, g_ctxs);
    cudaGetSymbolAddress((void**)&Was,  g_Was);
    cudaGetSymbolAddress((void**)&Wihs, g_Wihs);
    cudaGetSymbolAddress((void**)&embs, g_embs);
    const size_t CTXN = (size_t)BATCH * LCTX * CTXD;
    const size_t WAN  = (size_t)HID * CTXD;
    const size_t WIHN = (size_t)G3H * XDIM;
    const size_t EMBN = (size_t)BATCH * TSTEPS * EMB;
    __half* c1 = ctxs; __half* c2 = ctxs + CTXN;
    __half* w1 = Was;  __half* w2 = Was + WAN;
    __half* i1 = Wihs; __half* i2 = Wihs + WIHN;
    __half* e1 = embs; __half* e2 = embs + EMBN;

    // 2-way fp16 splits (x256 pre-scale)
    k_split<<<CTXN / 1024, 256>>>(ctx, c1, c2);
    k_split<<<WAN  / 1024, 256>>>(Wa,  w1, w2);
    k_split<<<WIHN / 1024, 256>>>(Wih, i1, i2);
    k_split_emb<<<BATCH * TSTEPS, 128>>>(emb, tgt);

    // tensor-core precompute GEMMs (3-term fp16 split + fp32 re-accumulation)
    k_mma_gemm<<<dim3(G3H / 128, BATCH * TSTEPS / 128), 256, GSMEM>>>(
        e1, e2, EMB, i1, i2, XDIM, EMB, bih, gxe, G3H);
    k_mma_gemm<<<dim3(HID / 128, BATCH * LCTX / 128), 256, GSMEM>>>(
        c1, c2, CTXD, w1, w2, CTXD, CTXD, nullptr, ctxW, HID);
    k_mma_gemm<<<dim3(G3H / 128, BATCH * LCTX / 128), 256, GSMEM>>>(
        c1, c2, CTXD, i1 + EMB, i2 + EMB, XDIM, CTXD, nullptr, ctxP, G3H);

    // Prologue: seed h = h0
    k_seed<<<BATCH * HID / 256, 256>>>(h0);

    for (int t = 0; t < TSTEPS; t++) {
        k_stepA<<<256, 512>>>(Whh, bhh, ctx_len);   // gh(t) + scores/softmax(t)
        k_stepB<<<256, 256>>>(t, out);              // gxc(t) + GRU -> h(t+1), out
    }
}

// round 17
// speedup vs baseline: 1.3005x; 1.3005x over previous
#include <cuda_runtime.h>
#include <cuda_fp16.h>
#include <cstdint>

#define VOCAB 32000
#define EMB   512
#define HID   1024
#define CTXD  2048
#define BATCH 64
#define TSTEPS 64
#define LCTX  64
#define XDIM  (EMB + CTXD)   // 2560
#define G3H   (3 * HID)      // 3072

#define SCALE     256.0f
#define INV_SCALE (1.0f / 65536.0f)

// ---------------------------------------------------------------------------
// Device-global scratch
// ---------------------------------------------------------------------------
__device__ float g_ctxW[BATCH * LCTX * HID];
__device__ float g_ctxP[BATCH * LCTX * G3H];
__device__ float g_gxe [BATCH * TSTEPS * G3H];
__device__ float g_gxc [BATCH * G3H];
__device__ float g_gh4 [4][BATCH * G3H];
__device__ float g_h   [BATCH * HID];

// fp16 2-way split buffers (hi / lo), pre-scaled by 256
__device__ __half g_ctxs[2][BATCH * LCTX * CTXD];
__device__ __half g_Was [2][HID * CTXD];
__device__ __half g_Wihs[2][G3H * XDIM];
__device__ __half g_embs[2][BATCH * TSTEPS * EMB];

// ---------------------------------------------------------------------------
// helpers
// ---------------------------------------------------------------------------
__device__ __forceinline__ uint32_t smem_u32(const void* p) {
    uint32_t a;
    asm("{ .reg .u64 t; cvta.to.shared.u64 t, %1; cvt.u32.u64 %0, t; }" : "=r"(a) : "l"(p));
    return a;
}

__device__ __forceinline__ void ldmx4(uint32_t& r0, uint32_t& r1, uint32_t& r2, uint32_t& r3,
                                      uint32_t addr) {
    asm volatile("ldmatrix.sync.aligned.m8n8.x4.shared.b16 {%0,%1,%2,%3}, [%4];"
                 : "=r"(r0), "=r"(r1), "=r"(r2), "=r"(r3) : "r"(addr));
}

__device__ __forceinline__ void mma16816h(float* c, const uint32_t* a, const uint32_t* b) {
    asm volatile("mma.sync.aligned.m16n8k16.row.col.f32.f16.f16.f32 "
        "{%0,%1,%2,%3}, {%4,%5,%6,%7}, {%8,%9}, {%0,%1,%2,%3};"
        : "+f"(c[0]), "+f"(c[1]), "+f"(c[2]), "+f"(c[3])
        : "r"(a[0]), "r"(a[1]), "r"(a[2]), "r"(a[3]), "r"(b[0]), "r"(b[1]));
}

__device__ __forceinline__ void cp16(uint32_t dst, const void* src) {
    asm volatile("cp.async.cg.shared.global [%0], [%1], 16;" :: "r"(dst), "l"(src));
}
#define CP_COMMIT() asm volatile("cp.async.commit_group;" ::: "memory")
#define CP_WAIT1()  asm volatile("cp.async.wait_group 1;" ::: "memory")
#define CP_WAIT0()  asm volatile("cp.async.wait_group 0;" ::: "memory")

// ---------------------------------------------------------------------------
// Split fp32 -> 2x fp16 (hi, lo) with x256 pre-scale
// ---------------------------------------------------------------------------
__device__ __forceinline__ void split2(float x, __half& h, __half& l) {
    float xs = x * SCALE;
    h = __float2half_rn(xs);
    float r = xs - __half2float(h);
    l = __float2half_rn(r);
}

__global__ void k_split(const float* __restrict__ s,
                        __half* __restrict__ d0,
                        __half* __restrict__ d1)
{
    int i = blockIdx.x * 256 + threadIdx.x;
    float4 v = ((const float4*)s)[i];
    __half h[4], l[4];
    float x[4] = {v.x, v.y, v.z, v.w};
#pragma unroll
    for (int q = 0; q < 4; q++) split2(x[q], h[q], l[q]);
    ((uint2*)d0)[i] = *(uint2*)h;
    ((uint2*)d1)[i] = *(uint2*)l;
}

__global__ void k_split_emb(const float* __restrict__ emb, const int* __restrict__ tgt)
{
    int row = blockIdx.x;
    int tok = tgt[row];
    int c = threadIdx.x;
    float4 v = ((const float4*)(emb + (size_t)tok * EMB))[c];
    __half h[4], l[4];
    float x[4] = {v.x, v.y, v.z, v.w};
#pragma unroll
    for (int q = 0; q < 4; q++) split2(x[q], h[q], l[q]);
    ((uint2*)(g_embs[0] + (size_t)row * EMB))[c] = *(uint2*)h;
    ((uint2*)(g_embs[1] + (size_t)row * EMB))[c] = *(uint2*)l;
}

// ---------------------------------------------------------------------------
// Fused precompute: ALL THREE GEMMs in one launch (1792 CTAs).
//   bx in [0,768):     ctxP = ctx @ Wih[:,512:]^T        (K=2048, 24 n-tiles)
//   bx in [768,1024):  ctxW = ctx @ Wa^T                 (K=2048,  8 n-tiles)
//   bx in [1024,1792): gxe  = emb[tgt] @ Wih[:,:512]^T+b (K=512,  24 n-tiles)
// Long-K CTAs first so short gxe CTAs backfill the tail.
// Per-tile math identical to R15's k_mma_gemm (3-term fp16 split + fp32
// re-accumulation, cp.async 2-stage) => bit-identical outputs.
// ---------------------------------------------------------------------------
#define ROWB 80
#define TILEB (128 * ROWB)
#define STAGEB (4 * TILEB)
#define GSMEM (2 * STAGEB)

__global__ void __launch_bounds__(256) k_mma_all(
    const __half* __restrict__ c1, const __half* __restrict__ c2,
    const __half* __restrict__ w1, const __half* __restrict__ w2,
    const __half* __restrict__ i1, const __half* __restrict__ i2,
    const __half* __restrict__ e1, const __half* __restrict__ e2,
    const float* __restrict__ bih,
    float* __restrict__ ctxP, float* __restrict__ ctxW, float* __restrict__ gxe)
{
    extern __shared__ __align__(16) char smem[];

    const int bx = blockIdx.x;
    const int tid = threadIdx.x;
    const int w = tid >> 5, lane = tid & 31;
    const int wm = w >> 2, wn = w & 3;

    // dispatch
    const __half *A1, *A2, *B1, *B2;
    int lda, ldb, K, ldc, m0, n0;
    const float* bias;
    float* C;
    if (bx < 768) {              // ctxP
        A1 = c1; A2 = c2; lda = CTXD;
        B1 = i1 + EMB; B2 = i2 + EMB; ldb = XDIM;
        K = CTXD; bias = nullptr; C = ctxP; ldc = G3H;
        n0 = (bx % 24) * 128; m0 = (bx / 24) * 128;
    } else if (bx < 1024) {      // ctxW
        int idx = bx - 768;
        A1 = c1; A2 = c2; lda = CTXD;
        B1 = w1; B2 = w2; ldb = CTXD;
        K = CTXD; bias = nullptr; C = ctxW; ldc = HID;
        n0 = (idx % 8) * 128; m0 = (idx / 8) * 128;
    } else {                     // gxe
        int idx = bx - 1024;
        A1 = e1; A2 = e2; lda = EMB;
        B1 = i1; B2 = i2; ldb = XDIM;
        K = EMB; bias = bih; C = gxe; ldc = G3H;
        n0 = (idx % 24) * 128; m0 = (idx / 24) * 128;
    }

    const uint32_t sbase = smem_u32(smem);
    const uint32_t aoff = (uint32_t)(wm * 64 + (lane & 15)) * ROWB + (lane >> 4) * 16;
    const uint32_t boff = (uint32_t)(wn * 32 + ((lane >> 4) & 1) * 8 + (lane & 7)) * ROWB
                        + ((lane >> 3) & 1) * 16;

    const int r0 = tid >> 2, kc0 = tid & 3;
    const int r1 = (tid + 256) >> 2;
    const uint32_t d0 = (uint32_t)r0 * ROWB + kc0 * 16;
    const uint32_t d1 = (uint32_t)r1 * ROWB + kc0 * 16;

    const __half* pa[8] = {
        A1 + (size_t)(m0 + r0) * lda + kc0 * 8, A1 + (size_t)(m0 + r1) * lda + kc0 * 8,
        A2 + (size_t)(m0 + r0) * lda + kc0 * 8, A2 + (size_t)(m0 + r1) * lda + kc0 * 8,
        B1 + (size_t)(n0 + r0) * ldb + kc0 * 8, B1 + (size_t)(n0 + r1) * ldb + kc0 * 8,
        B2 + (size_t)(n0 + r0) * ldb + kc0 * 8, B2 + (size_t)(n0 + r1) * ldb + kc0 * 8 };

    auto issue = [&](int stage, int k0) {
        const uint32_t sb = sbase + stage * STAGEB;
#pragma unroll
        for (int q = 0; q < 4; q++) {
            cp16(sb + q * TILEB + d0, pa[2 * q]     + k0);
            cp16(sb + q * TILEB + d1, pa[2 * q + 1] + k0);
        }
    };

    float master[4][4][4];
#pragma unroll
    for (int i = 0; i < 4; i++)
#pragma unroll
        for (int j = 0; j < 4; j++)
#pragma unroll
            for (int q = 0; q < 4; q++) master[i][j][q] = 0.f;

    const int NC = K / 32;

    issue(0, 0);
    CP_COMMIT();

    for (int c = 0; c < NC; c++) {
        if (c + 1 < NC) {
            issue((c + 1) & 1, (c + 1) * 32);
            CP_COMMIT();
            CP_WAIT1();
        } else {
            CP_WAIT0();
        }
        __syncthreads();

        const uint32_t sb = sbase + (c & 1) * STAGEB;
        const uint32_t sA1 = sb, sA2 = sb + TILEB;
        const uint32_t sB1 = sb + 2 * TILEB, sB2 = sb + 3 * TILEB;

#pragma unroll
        for (int k16 = 0; k16 < 2; k16++) {
            const uint32_t kadd = k16 * 32;
            uint32_t b1f[8], b2f[8];
            ldmx4(b1f[0], b1f[1], b1f[2], b1f[3], sB1 + boff + kadd);
            ldmx4(b1f[4], b1f[5], b1f[6], b1f[7], sB1 + boff + kadd + 16 * ROWB);
            ldmx4(b2f[0], b2f[1], b2f[2], b2f[3], sB2 + boff + kadd);
            ldmx4(b2f[4], b2f[5], b2f[6], b2f[7], sB2 + boff + kadd + 16 * ROWB);
#pragma unroll
            for (int mi = 0; mi < 4; mi++) {
                uint32_t a1f[4], a2f[4];
                ldmx4(a1f[0], a1f[1], a1f[2], a1f[3], sA1 + aoff + mi * 16 * ROWB + kadd);
                ldmx4(a2f[0], a2f[1], a2f[2], a2f[3], sA2 + aoff + mi * 16 * ROWB + kadd);
#pragma unroll
                for (int ni = 0; ni < 4; ni++) {
                    float t0[4] = {0.f, 0.f, 0.f, 0.f};
                    float t1[4] = {0.f, 0.f, 0.f, 0.f};
                    mma16816h(t0, a2f, b1f + ni * 2);   // ~2^-12
                    mma16816h(t1, a1f, b2f + ni * 2);   // ~2^-12 (indep chain)
                    mma16816h(t0, a1f, b1f + ni * 2);   // ~1 (only full-mag add)
#pragma unroll
                    for (int q = 0; q < 4; q++)
                        master[mi][ni][q] += t0[q] + t1[q];
                }
            }
        }
        __syncthreads();
    }

    const int lr = lane >> 2, lc = (lane & 3) * 2;
#pragma unroll
    for (int mi = 0; mi < 4; mi++) {
#pragma unroll
        for (int ni = 0; ni < 4; ni++) {
            int n = n0 + wn * 32 + ni * 8 + lc;
            float bv0 = bias ? bias[n]     : 0.f;
            float bv1 = bias ? bias[n + 1] : 0.f;
            int mA = m0 + wm * 64 + mi * 16 + lr;
            float2 v0 = {master[mi][ni][0] * INV_SCALE + bv0,
                         master[mi][ni][1] * INV_SCALE + bv1};
            float2 v1 = {master[mi][ni][2] * INV_SCALE + bv0,
                         master[mi][ni][3] * INV_SCALE + bv1};
            *(float2*)(C + (size_t)mA * ldc + n)       = v0;
            *(float2*)(C + (size_t)(mA + 8) * ldc + n) = v1;
        }
    }
}

// ---------------------------------------------------------------------------
// K2: per step, 256 CTAs x 512 threads (EXACT R15 structure — best loop).
//  bx < 192: gh quarter-GEMM (kh = bx & 3, 64-col n-tile, K = 256).
//  bx >= 192: attn CTA b: scores -> softmax -> gxc = attn @ ctxP.
// ---------------------------------------------------------------------------
#define PAD 68

__global__ void __launch_bounds__(512) k_step(
    const float* __restrict__ Whh,
    const float* __restrict__ bhh,
    const int* __restrict__ ctx_len)
{
    const int bx = blockIdx.x;
    const int tid = threadIdx.x;

    if (bx < 192) {
        __shared__ __align__(16) float Xs[32 * PAD];
        __shared__ __align__(16) float Ws[32 * PAD];
        const int kh = bx & 3;
        const int n0 = (bx >> 2) * 64;
        const float* A  = g_h + kh * 256;
        const float* Bw = Whh + kh * 256;

        const int tm = tid >> 4, tn = tid & 15;
        const int lrow = tid >> 3, lkc = tid & 7;

        float acc[2][4];
#pragma unroll
        for (int i = 0; i < 2; i++)
#pragma unroll
            for (int j = 0; j < 4; j++) acc[i][j] = 0.f;

        for (int k0 = 0; k0 < 256; k0 += 32) {
            float4 v = *(const float4*)(A + (size_t)lrow * HID + k0 + lkc * 4);
            Xs[(lkc * 4 + 0) * PAD + lrow] = v.x;
            Xs[(lkc * 4 + 1) * PAD + lrow] = v.y;
            Xs[(lkc * 4 + 2) * PAD + lrow] = v.z;
            Xs[(lkc * 4 + 3) * PAD + lrow] = v.w;
            float4 w = *(const float4*)(Bw + (size_t)(n0 + lrow) * HID + k0 + lkc * 4);
            Ws[(lkc * 4 + 0) * PAD + lrow] = w.x;
            Ws[(lkc * 4 + 1) * PAD + lrow] = w.y;
            Ws[(lkc * 4 + 2) * PAD + lrow] = w.z;
            Ws[(lkc * 4 + 3) * PAD + lrow] = w.w;
            __syncthreads();
#pragma unroll
            for (int kk = 0; kk < 32; kk++) {
                float a0 = Xs[kk * PAD + tm * 2];
                float a1 = Xs[kk * PAD + tm * 2 + 1];
                float b[4];
                *(float4*)b = *(const float4*)&Ws[kk * PAD + tn * 4];
#pragma unroll
                for (int j = 0; j < 4; j++) {
                    acc[0][j] = fmaf(a0, b[j], acc[0][j]);
                    acc[1][j] = fmaf(a1, b[j], acc[1][j]);
                }
            }
            __syncthreads();
        }

        float* dst = g_gh4[kh];
#pragma unroll
        for (int i = 0; i < 2; i++) {
            int m = tm * 2 + i;
            int n = n0 + tn * 4;
            float4 v;
            v.x = acc[i][0]; v.y = acc[i][1]; v.z = acc[i][2]; v.w = acc[i][3];
            if (kh == 0) {
                v.x += bhh[n]; v.y += bhh[n + 1]; v.z += bhh[n + 2]; v.w += bhh[n + 3];
            }
            *(float4*)(dst + (size_t)m * G3H + n) = v;
        }
        return;
    }

    // ---- attention CTA ----
    const int b = bx - 192;
    __shared__ __align__(16) float h_s[HID];
    __shared__ float attn_s[LCTX];

    ((float2*)h_s)[tid] = ((const float2*)(g_h + (size_t)b * HID))[tid];
    __syncthreads();

    const int w = tid >> 5, lane = tid & 31;
    const float4* h4 = (const float4*)h_s;
#pragma unroll
    for (int li = 0; li < 4; li++) {
        const int l = li * 16 + w;
        const float4* cw = (const float4*)(g_ctxW + ((size_t)b * LCTX + l) * HID);
        float s = 0.f;
#pragma unroll 8
        for (int i = lane; i < HID / 4; i += 32) {
            float4 a = h4[i], v = cw[i];
            s += a.x * v.x + a.y * v.y + a.z * v.z + a.w * v.w;
        }
#pragma unroll
        for (int off = 16; off > 0; off >>= 1)
            s += __shfl_xor_sync(0xffffffffu, s, off);
        if (lane == 0) attn_s[l] = s;
    }
    __syncthreads();

    if (tid < 32) {
        int len = ctx_len[b];
        float s0 = (tid < len)      ? attn_s[tid]      : -1e9f;
        float s1 = (tid + 32 < len) ? attn_s[tid + 32] : -1e9f;
        float m = fmaxf(s0, s1);
#pragma unroll
        for (int off = 16; off > 0; off >>= 1)
            m = fmaxf(m, __shfl_xor_sync(0xffffffffu, m, off));
        float e0 = __expf(s0 - m), e1 = __expf(s1 - m);
        float ss = e0 + e1;
#pragma unroll
        for (int off = 16; off > 0; off >>= 1)
            ss += __shfl_xor_sync(0xffffffffu, ss, off);
        attn_s[tid]      = e0 / ss;
        attn_s[tid + 32] = e1 / ss;
    }
    __syncthreads();

    float acc[6];
#pragma unroll
    for (int q = 0; q < 6; q++) acc[q] = 0.f;
    const float* base = g_ctxP + ((size_t)b * LCTX) * G3H + tid;
#pragma unroll 4
    for (int l = 0; l < LCTX; l++) {
        float a = attn_s[l];
        const float* row = base + (size_t)l * G3H;
#pragma unroll
        for (int q = 0; q < 6; q++)
            acc[q] = fmaf(a, row[q * 512], acc[q]);
    }
    float* dst = g_gxc + (size_t)b * G3H + tid;
#pragma unroll
    for (int q = 0; q < 6; q++) dst[q * 512] = acc[q];
}

// ---------------------------------------------------------------------------
// K1: pure GRU elementwise, 4x parallel (exact R15).
// ---------------------------------------------------------------------------
__global__ void k_gru(int t,
                      const float* __restrict__ h0,
                      float* __restrict__ out)
{
    const int bx = blockIdx.x;
    const int b = bx >> 2, sl = bx & 3;
    const int j = sl * 256 + threadIdx.x;

    if (t < 0) {
        g_h[(size_t)b * HID + j] = h0[(size_t)b * HID + j];
        return;
    }

    const float* gxe = g_gxe + (size_t)(b * TSTEPS + t) * G3H;
    const float* gxc = g_gxc + (size_t)b * G3H;
    float* hp = g_h + (size_t)b * HID;

    float gxr = gxe[j]           + gxc[j];
    float gxz = gxe[HID + j]     + gxc[HID + j];
    float gxn = gxe[2 * HID + j] + gxc[2 * HID + j];
    float ghr = 0.f, ghz = 0.f, ghn = 0.f;
#pragma unroll
    for (int kh = 0; kh < 4; kh++) {
        const float* gh = g_gh4[kh] + (size_t)b * G3H;
        ghr += gh[j];
        ghz += gh[HID + j];
        ghn += gh[2 * HID + j];
    }
    float r = 1.f / (1.f + __expf(-(gxr + ghr)));
    float z = 1.f / (1.f + __expf(-(gxz + ghz)));
    float n = tanhf(gxn + r * ghn);
    float hv = (1.f - z) * n + z * hp[j];

    hp[j] = hv;
    out[((size_t)b * TSTEPS + t) * HID + j] = hv;
    if (t == TSTEPS - 1)
        out[(size_t)BATCH * TSTEPS * HID + (size_t)b * HID + j] = hv;
}

// ---------------------------------------------------------------------------
extern "C" void kernel_launch(void* const* d_in, const int* in_sizes, int n_in,
                              void* d_out, int out_size)
{
    const int*   tgt     = (const int*)  d_in[0];
    const float* ctx     = (const float*)d_in[1];
    const float* h0      = (const float*)d_in[2];
    const int*   ctx_len = (const int*)  d_in[3];
    const float* emb     = (const float*)d_in[4];
    const float* Wa      = (const float*)d_in[5];
    const float* Wih     = (const float*)d_in[6];
    const float* Whh     = (const float*)d_in[7];
    const float* bih     = (const float*)d_in[8];
    const float* bhh     = (const float*)d_in[9];
    float* out = (float*)d_out;

    cudaFuncSetAttribute(k_mma_all, cudaFuncAttributeMaxDynamicSharedMemorySize, GSMEM);

    float* ctxW = nullptr; cudaGetSymbolAddress((void**)&ctxW, g_ctxW);
    float* ctxP = nullptr; cudaGetSymbolAddress((void**)&ctxP, g_ctxP);
    float* gxe  = nullptr; cudaGetSymbolAddress((void**)&gxe,  g_gxe);

    __half *ctxs, *Was, *Wihs, *embs;
    cudaGetSymbolAddress((void**)&ctxs, g_ctxs);
    cudaGetSymbolAddress((void**)&Was,  g_Was);
    cudaGetSymbolAddress((void**)&Wihs, g_Wihs);
    cudaGetSymbolAddress((void**)&embs, g_embs);
    const size_t CTXN = (size_t)BATCH * LCTX * CTXD;
    const size_t WAN  = (size_t)HID * CTXD;
    const size_t WIHN = (size_t)G3H * XDIM;
    const size_t EMBN = (size_t)BATCH * TSTEPS * EMB;
    __half* c1 = ctxs; __half* c2 = ctxs + CTXN;
    __half* w1 = Was;  __half* w2 = Was + WAN;
    __half* i1 = Wihs; __half* i2 = Wihs + WIHN;
    __half* e1 = embs; __half* e2 = embs + EMBN;

    // 2-way fp16 splits (x256 pre-scale)
    k_split<<<CTXN / 1024, 256>>>(ctx, c1, c2);
    k_split<<<WAN  / 1024, 256>>>(Wa,  w1, w2);
    k_split<<<WIHN / 1024, 256>>>(Wih, i1, i2);
    k_split_emb<<<BATCH * TSTEPS, 128>>>(emb, tgt);

    // fused precompute: all three GEMMs in one launch (long-K CTAs first)
    k_mma_all<<<1792, 256, GSMEM>>>(c1, c2, w1, w2, i1, i2, e1, e2,
                                    bih, ctxP, ctxW, gxe);

    // Prologue: seed h = h0
    k_gru<<<BATCH * 4, 256>>>(-1, h0, out);

    for (int t = 0; t < TSTEPS; t++) {
        k_step<<<256, 512>>>(Whh, bhh, ctx_len);   // gh(t) + scores/softmax/gxc(t)
        k_gru<<<BATCH * 4, 256>>>(t, h0, out);     // h(t) -> h(t+1), out
    }
}